// round 13
// baseline (speedup 1.0000x reference)
#include <cuda_runtime.h>

// Problem constants: T=1024, B=64, I=512, H=512, 3H=1536
#define NCTA 128
#define NTEAMS 4        // 4 teams x 32 CTAs; team tau owns b in {tau, tau+4, ..., tau+60}
#define NTHR 768        // 24 warps: 6 rowgroups x 2 kslices x 2 bhalves

// ---------------- device-global scratch (no allocation allowed) ----------------
__device__ __align__(16) float g_h[2][NTEAMS][16][512]; // ping-pong h: [buf][team][team-b][k]
__device__ unsigned int g_flag[NCTA];                // per-CTA publish counters (monotonic)

// ---------------- f32x2 packed-math helpers (Blackwell, PTX-only path) ----------
__device__ __forceinline__ void ffma2(unsigned long long &acc, unsigned long long a,
                                      unsigned long long b) {
    asm("fma.rn.f32x2 %0, %1, %2, %0;" : "+l"(acc) : "l"(a), "l"(b));
}
__device__ __forceinline__ float sum2(unsigned long long v) {
    float lo, hi; asm("mov.b64 {%0, %1}, %2;" : "=f"(lo), "=f"(hi) : "l"(v)); return lo + hi;
}

// ---------------- flag primitives (gpu scope, L2-coherent) -----------------------
__device__ __forceinline__ unsigned int ld_acq(const unsigned int* p) {
    unsigned int v;
    asm volatile("ld.acquire.gpu.global.u32 %0, [%1];" : "=r"(v) : "l"(p) : "memory");
    return v;
}
__device__ __forceinline__ unsigned int ld_rlx(const unsigned int* p) {
    unsigned int v;
    asm volatile("ld.relaxed.gpu.global.u32 %0, [%1];" : "=r"(v) : "l"(p) : "memory");
    return v;
}
__device__ __forceinline__ void st_rel(unsigned int* p, unsigned int v) {
    asm volatile("st.release.gpu.global.u32 [%0], %1;" :: "l"(p), "r"(v) : "memory");
}
__device__ __forceinline__ void bar_sync(int id, int cnt) {
    asm volatile("bar.sync %0, %1;" :: "r"(id), "r"(cnt) : "memory");
}

// ---------------- dynamic SMEM layout (floats) -----------------------------------
#define WHH_OFF  0                           // W_hh slice: [48 rows][512]   (98,304 B)
#define HS_OFF   (48 * 512)                  // staged h: [16 b][512]        (32,768 B)
#define RED_OFF  (HS_OFF + 16 * 512)         // red: [2 par][2 ks][48][17]   (13,056 B)
#define RING_OFF (RED_OFF + 2 * 2 * 48 * 17) // gx ring: [4 slot][2 ks][48][17] (26,112 B)
#define LENS_OFF (RING_OFF + 4 * 2 * 48 * 17)
#define SMEM_FLOATS (LENS_OFF + 16)
#define SMEM_BYTES  (SMEM_FLOATS * 4)        // ~170.3 KB
#define RED_AT(par, ksi, row, b)   sm[RED_OFF  + (((par)  * 2 + (ksi)) * 48 + (row)) * 17 + (b)]
#define RING_AT(slot, ksi, row, b) sm[RING_OFF + (((slot) * 2 + (ksi)) * 48 + (row)) * 17 + (b)]

// =================================================================================
// Fused persistent GRU: the input projection (x @ W_ih^T) is computed in-kernel,
// 2 steps ahead, into an SMEM ring -- it has no h dependence, so it fills the idle
// window while waiting for peer CTAs' h(t) flags. No separate GEMM, no gx buffer.
//   4 teams x 32 CTAs; team tau owns b = 4i + tau; CTA owns units [16c,16c+16).
//   Warp = rowgroup(6 x 8 rows) x kslice(2 x 256 k) x bhalf(2 x 8 b).
//   Lane = q(8 k-subs of 4) x p(4 b-pairs).
// =================================================================================
__global__ __launch_bounds__(NTHR, 1) void gru_fused(const float* __restrict__ x,
                                                     const float* __restrict__ wih,
                                                     const float* __restrict__ whh,
                                                     const float* __restrict__ bih,
                                                     const float* __restrict__ bhh,
                                                     const int* __restrict__ lens,
                                                     float* __restrict__ out) {
    extern __shared__ __align__(16) float sm[];
    int* sm_lens = (int*)&sm[LENS_OFF];

    const int tid  = threadIdx.x;
    const int tau  = blockIdx.x >> 5;        // team 0..3
    const int c    = blockIdx.x & 31;        // CTA within team
    const int wrp  = tid >> 5;
    const int lane = tid & 31;

    // FMA-phase warp mapping
    const int rg = wrp >> 2;                 // rowgroup 0..5 (8 rows each)
    const int ks = (wrp >> 1) & 1;           // kslice 0..1 (256 k each)
    const int bh = wrp & 1;                  // bhalf 0..1 (8 b each)
    const int q  = lane >> 2;                // k-sub 0..7 (4 k per i-iter)
    const int p  = lane & 3;                 // b-pair 0..3
    const int b0 = bh * 8 + 2 * p;           // team-b
    const int rowbase = rg * 8;

    // gate-phase mapping (tid < 256)
    const int gu = tid & 15;                 // unit-in-CTA
    const int gb = tid >> 4;                 // team-b (valid for tid < 256)
    const int bglob = 4 * (gb & 15) + tau;
    const int j = 16 * c + gu;

    // W_ih base for this warp's 8 rows (global row = g*512 + 16c + u)
    const float* wih_base = wih +
        ((size_t)((rg >> 1) * 512 + 16 * c + (rg & 1) * 8)) * 512;

    // ---- preload W_hh slice (48 rows x 512) into SMEM ----
    for (int idx = tid; idx < 48 * 128; idx += NTHR) {
        int row = idx >> 7;
        int k4  = (idx & 127) << 2;
        int g   = row >> 4;
        int u   = row & 15;
        *(float4*)&sm[WHH_OFF + row * 512 + k4] =
            *(const float4*)&whh[(size_t)(g * 512 + 16 * c + u) * 512 + k4];
    }
    if (tid < 16) sm_lens[tid] = lens[4 * tid + tau];

    const unsigned int F = ld_rlx(&g_flag[blockIdx.x]);  // monotonic across replays

    float bs_r = 0.f, bs_z = 0.f, bxn = 0.f, bhn = 0.f;
    if (tid < 256) {
        bs_r = bhh[j] + bih[j];              // r/z: biases fold together
        bs_z = bhh[512 + j] + bih[512 + j];
        bxn  = bih[1024 + j];                // n: keep separate (r * gh_n factor)
        bhn  = bhh[1024 + j];
    }
    // h(0) = 0 for this CTA's units across all team-b
    if (tid < 256)
        __stcg(&g_h[0][tau][gb][j], 0.f);
    __syncthreads();
    const int maxlen_team = sm_lens[0];
    const int ml_bh = sm_lens[bh * 8];       // warp b-half max length (descending)
    const int len_b = (tid < 256) ? sm_lens[gb] : 0;
    if (tid == 0) st_rel(&g_flag[blockIdx.x], F + 1);    // h(0) published

    const unsigned int* fp = &g_flag[(tau << 5) + lane];
    float hreg = 0.f;

    // ---------------- gx compute (input projection) for step tt -> ring ----------
    auto gx_compute = [&](int tt) {
        unsigned long long accA[8], accB[8];
#pragma unroll
        for (int r = 0; r < 8; r++) { accA[r] = 0ull; accB[r] = 0ull; }
        const float* xrA = x + ((size_t)tt * 64 + 4 * b0 + tau) * 512;
        const float* xrB = xrA + 4 * 512;    // next team-b = +4 global b
#pragma unroll
        for (int i = 0; i < 8; i++) {
            int ko = ks * 256 + (i * 8 + q) * 4;
            ulonglong2 xA = __ldg((const ulonglong2*)(xrA + ko));
            ulonglong2 xB = __ldg((const ulonglong2*)(xrB + ko));
#pragma unroll
            for (int r = 0; r < 8; r++) {
                ulonglong2 wv = __ldg((const ulonglong2*)(wih_base + (size_t)r * 512 + ko));
                ffma2(accA[r], xA.x, wv.x);
                ffma2(accA[r], xA.y, wv.y);
                ffma2(accB[r], xB.x, wv.x);
                ffma2(accB[r], xB.y, wv.y);
            }
        }
        const int slot = tt & 3;
#pragma unroll
        for (int r = 0; r < 8; r++) {
            float sA = sum2(accA[r]);
            float sB = sum2(accB[r]);
            sA += __shfl_xor_sync(0xffffffffu, sA, 4);
            sB += __shfl_xor_sync(0xffffffffu, sB, 4);
            sA += __shfl_xor_sync(0xffffffffu, sA, 8);
            sB += __shfl_xor_sync(0xffffffffu, sB, 8);
            sA += __shfl_xor_sync(0xffffffffu, sA, 16);
            sB += __shfl_xor_sync(0xffffffffu, sB, 16);
            if (lane < 4) {
                RING_AT(slot, ks, rowbase + r, b0)     = sA;
                RING_AT(slot, ks, rowbase + r, b0 + 1) = sB;
            }
        }
    };

    // Prologue: gx(0), gx(1) into ring slots 0,1 (overlaps other CTAs' startup)
    if (0 < ml_bh) gx_compute(0);
    if (1 < ml_bh) gx_compute(1);
    __syncthreads();

    for (int t = 0; t < 1024; t++) {
        if (t < maxlen_team) {
            // [gx] step t+2's input projection -- no h dependence, fills the wait
            const int t2 = t + 2;
            if (t2 < ml_bh) gx_compute(t2);

            // [poll] warp 0 ONLY waits for all 32 team CTAs to publish h(t)
            if (wrp == 0) {
                const unsigned int tgt = F + 1 + (unsigned)t;
                while (!__all_sync(0xffffffffu, ld_acq(fp) >= tgt)) {}
            }
            __syncthreads();

            // [stage] team h(t): 16 b x 512 k, contiguous float4 copies
            for (int s = tid; s < 2048; s += NTHR) {
                int row  = s >> 7;
                int col4 = (s & 127) << 2;
                float4 v = __ldcg((const float4*)&g_h[t & 1][tau][row][col4]);
                *(float4*)&sm[HS_OFF + row * 512 + col4] = v;
            }
            __syncthreads();

            // [h-FMA] 8 rows x 32 k x 2 b per lane (skip if b-half done)
            if (t < ml_bh) {
                unsigned long long accA[8], accB[8];
#pragma unroll
                for (int r = 0; r < 8; r++) { accA[r] = 0ull; accB[r] = 0ull; }

                const float* hr0 = &sm[HS_OFF + b0 * 512];
                const float* hr1 = hr0 + 512;
#pragma unroll
                for (int i = 0; i < 8; i++) {
                    int ko = ks * 256 + (i * 8 + q) * 4;   // 4 consecutive k
                    ulonglong2 hA = *(const ulonglong2*)&hr0[ko];
                    ulonglong2 hB = *(const ulonglong2*)&hr1[ko];
#pragma unroll
                    for (int r = 0; r < 8; r++) {
                        ulonglong2 wv = *(const ulonglong2*)
                            &sm[WHH_OFF + (rowbase + r) * 512 + ko];
                        ffma2(accA[r], hA.x, wv.x);
                        ffma2(accA[r], hA.y, wv.y);
                        ffma2(accB[r], hB.x, wv.x);
                        ffma2(accB[r], hB.y, wv.y);
                    }
                }

                // fold k-parity + q (xor 4,8,16); q==0 lanes store partials
#pragma unroll
                for (int r = 0; r < 8; r++) {
                    float sA = sum2(accA[r]);
                    float sB = sum2(accB[r]);
                    sA += __shfl_xor_sync(0xffffffffu, sA, 4);
                    sB += __shfl_xor_sync(0xffffffffu, sB, 4);
                    sA += __shfl_xor_sync(0xffffffffu, sA, 8);
                    sB += __shfl_xor_sync(0xffffffffu, sB, 8);
                    sA += __shfl_xor_sync(0xffffffffu, sA, 16);
                    sB += __shfl_xor_sync(0xffffffffu, sB, 16);
                    if (lane < 4) {
                        RED_AT(t & 1, ks, rowbase + r, b0)     = sA;
                        RED_AT(t & 1, ks, rowbase + r, b0 + 1) = sB;
                    }
                }
            }
            __syncthreads();                   // red[t&1] + ring slot complete

            // [gate] 16 units x 16 team-b; gx from ring slot t&3
            if (tid < 256) {
                float outv = 0.f;
                if (t < len_b) {
                    const int sl = t & 3;
                    float ar = bs_r + RED_AT(t & 1, 0, gu, gb)      + RED_AT(t & 1, 1, gu, gb)
                                    + RING_AT(sl, 0, gu, gb)        + RING_AT(sl, 1, gu, gb);
                    float az = bs_z + RED_AT(t & 1, 0, 16 + gu, gb) + RED_AT(t & 1, 1, 16 + gu, gb)
                                    + RING_AT(sl, 0, 16 + gu, gb)   + RING_AT(sl, 1, 16 + gu, gb);
                    float ghn = bhn + RED_AT(t & 1, 0, 32 + gu, gb) + RED_AT(t & 1, 1, 32 + gu, gb);
                    float gxn = bxn + RING_AT(sl, 0, 32 + gu, gb)   + RING_AT(sl, 1, 32 + gu, gb);
                    float r = 1.f / (1.f + __expf(-ar));
                    float z = 1.f / (1.f + __expf(-az));
                    float n = tanhf(gxn + r * ghn);
                    hreg = (1.f - z) * n + z * hreg;
                    outv = hreg;
                }
                // publish h(t+1): one scalar L2 store per (b, unit)
                __stcg(&g_h[(t + 1) & 1][tau][gb][j], hreg);
                bar_sync(1, 256);              // all gate h publishes done
                if (tid == 0) st_rel(&g_flag[blockIdx.x], F + 2 + (unsigned)t);

                out[(size_t)t * 32768 + bglob * 512 + j] = outv;   // off critical path
            }
        } else {
            // whole team finished: zero-fill remaining output rows (uniform branch)
            if (tid < 256)
                out[(size_t)t * 32768 + bglob * 512 + j] = 0.f;
        }
    }

    // h_last: [1, B, H]
    if (tid < 256)
        out[(size_t)1024 * 32768 + bglob * 512 + j] = hreg;
}

// =================================================================================
// Inputs (metadata order): x[T,B,I] f32, batch_lengths[B] i32, w_ih[3H,I] f32,
// w_hh[3H,H] f32, b_ih[3H] f32, b_hh[3H] f32.  Output: [T,B,H] then [1,B,H], fp32.
// =================================================================================
extern "C" void kernel_launch(void* const* d_in, const int* in_sizes, int n_in,
                              void* d_out, int out_size) {
    const float* x   = (const float*)d_in[0];
    const int*   len = (const int*)  d_in[1];
    const float* wih = (const float*)d_in[2];
    const float* whh = (const float*)d_in[3];
    const float* bih = (const float*)d_in[4];
    const float* bhh = (const float*)d_in[5];
    float* out = (float*)d_out;

    (void)in_sizes; (void)n_in; (void)out_size;

    cudaFuncSetAttribute(gru_fused, cudaFuncAttributeMaxDynamicSharedMemorySize, SMEM_BYTES);

    gru_fused<<<NCTA, NTHR, SMEM_BYTES>>>(x, wih, whh, bih, bhh, len, out);
}

// round 14
// speedup vs baseline: 1.4114x; 1.4114x over previous
#include <cuda_runtime.h>

// Problem constants: T=1024, B=64, I=512, H=512, 3H=1536
#define NCTA 128
#define NTEAMS 4        // 4 teams x 32 CTAs; team tau owns b in {tau, tau+4, ..., tau+60}
#define NTHR 768        // 24 warps: 6 rowgroups x 2 kslices x 2 bhalves

// ---------------- device-global scratch (no allocation allowed) ----------------
__device__ float g_gx[100663296];                      // [1024*64, 1536] input gate pre-acts
__device__ __align__(16) float g_hP[2][NTEAMS][256][32]; // [buf][team][kp][tb*2+par]
__device__ unsigned int g_flag[NCTA];                  // per-CTA publish counters (monotonic)

// ---------------- f32x2 packed-math helpers (Blackwell, PTX-only path) ----------
__device__ __forceinline__ void ffma2(unsigned long long &acc, unsigned long long a,
                                      unsigned long long b) {
    asm("fma.rn.f32x2 %0, %1, %2, %0;" : "+l"(acc) : "l"(a), "l"(b));
}
__device__ __forceinline__ unsigned long long dup2(float a) {
    unsigned long long r; asm("mov.b64 %0, {%1, %1};" : "=l"(r) : "f"(a)); return r;
}
__device__ __forceinline__ unsigned long long pack2(float lo, float hi) {
    unsigned long long r; asm("mov.b64 %0, {%1, %2};" : "=l"(r) : "f"(lo), "f"(hi)); return r;
}
__device__ __forceinline__ float sum2(unsigned long long v) {
    float lo, hi; asm("mov.b64 {%0, %1}, %2;" : "=f"(lo), "=f"(hi) : "l"(v)); return lo + hi;
}
__device__ __forceinline__ float2 unpack2(unsigned long long v) {
    float2 f; asm("mov.b64 {%0, %1}, %2;" : "=f"(f.x), "=f"(f.y) : "l"(v)); return f;
}

// ---------------- flag primitives (gpu scope, L2-coherent) -----------------------
__device__ __forceinline__ unsigned int ld_acq(const unsigned int* p) {
    unsigned int v;
    asm volatile("ld.acquire.gpu.global.u32 %0, [%1];" : "=r"(v) : "l"(p) : "memory");
    return v;
}
__device__ __forceinline__ unsigned int ld_rlx(const unsigned int* p) {
    unsigned int v;
    asm volatile("ld.relaxed.gpu.global.u32 %0, [%1];" : "=r"(v) : "l"(p) : "memory");
    return v;
}
__device__ __forceinline__ void st_rel(unsigned int* p, unsigned int v) {
    asm volatile("st.release.gpu.global.u32 [%0], %1;" :: "l"(p), "r"(v) : "memory");
}
__device__ __forceinline__ void bar_sync(int id, int cnt) {
    asm volatile("bar.sync %0, %1;" :: "r"(id), "r"(cnt) : "memory");
}

// ---------------- dynamic SMEM layout (floats) -- rec kernel (R10 layout) --------
#define WP_OFF   0                          // W: [48 rows][516]            (99,072 B)
#define WP_ROW   516
#define HS_OFF   (48 * 516)                 // staged h: [256 kp][36]       (36,864 B)
#define HS_ROW   36
#define RED_OFF  (HS_OFF + 256 * 36)        // red: [2 par][2 ks][48][17]   (13,056 B)
#define LENS_OFF (RED_OFF + 2 * 2 * 48 * 17)
#define SMEM_FLOATS (LENS_OFF + 16)
#define SMEM_BYTES  (SMEM_FLOATS * 4)
#define RED_AT(par, ksi, row, b) sm[RED_OFF + (((par) * 2 + (ksi)) * 48 + (row)) * 17 + (b)]

// =================================================================================
// Kernel A: gx[m][n] = sum_k X[m][k] * W[n][k] + bias[n]
//   X: [65536, 512], W: [1536, 512] -> g_gx. 128x128 tile, BK=8, 8x8 microtile.
//   DOUBLE-BUFFERED smem: one __syncthreads per k-chunk (was 2), LDG prefetch
//   for chunk i+1 issued before computing chunk i -> latency hidden by FMA.
// =================================================================================
__global__ __launch_bounds__(256) void gemm_gx(const float* __restrict__ X,
                                               const float* __restrict__ W,
                                               const float* __restrict__ bias) {
    __shared__ __align__(16) float As[2][8][128];
    __shared__ __align__(16) float Bs[2][8][128];
    const int tid = threadIdx.x;
    const int m0 = blockIdx.y * 128;
    const int n0 = blockIdx.x * 128;
    const int tx = tid & 15;
    const int ty = tid >> 4;
    const int lrow = tid >> 1;
    const int lk = (tid & 1) * 4;

    unsigned long long acc[8][4];
#pragma unroll
    for (int i = 0; i < 8; i++)
#pragma unroll
        for (int jp = 0; jp < 4; jp++) acc[i][jp] = 0ull;

    const float* xg = X + (size_t)(m0 + lrow) * 512 + lk;
    const float* wg = W + (size_t)(n0 + lrow) * 512 + lk;

    // prologue: chunk 0 -> buffer 0
    {
        float4 av = *(const float4*)(xg);
        float4 bv = *(const float4*)(wg);
        As[0][lk + 0][lrow] = av.x; As[0][lk + 1][lrow] = av.y;
        As[0][lk + 2][lrow] = av.z; As[0][lk + 3][lrow] = av.w;
        Bs[0][lk + 0][lrow] = bv.x; Bs[0][lk + 1][lrow] = bv.y;
        Bs[0][lk + 2][lrow] = bv.z; Bs[0][lk + 3][lrow] = bv.w;
    }
    __syncthreads();

    for (int k0 = 0; k0 < 512; k0 += 8) {
        const int buf  = (k0 >> 3) & 1;
        const int nbuf = buf ^ 1;
        const bool more = (k0 + 8) < 512;

        // prefetch next chunk (LDG issued before compute; lands during FMAs)
        float4 av, bv;
        if (more) {
            av = *(const float4*)(xg + k0 + 8);
            bv = *(const float4*)(wg + k0 + 8);
        }

#pragma unroll
        for (int kk = 0; kk < 8; kk++) {
            float4 a0 = *(const float4*)&As[buf][kk][ty * 8];
            float4 a1 = *(const float4*)&As[buf][kk][ty * 8 + 4];
            float4 b0 = *(const float4*)&Bs[buf][kk][tx * 8];
            float4 b1 = *(const float4*)&Bs[buf][kk][tx * 8 + 4];
            unsigned long long bp0 = pack2(b0.x, b0.y);
            unsigned long long bp1 = pack2(b0.z, b0.w);
            unsigned long long bp2 = pack2(b1.x, b1.y);
            unsigned long long bp3 = pack2(b1.z, b1.w);
            float a[8] = {a0.x, a0.y, a0.z, a0.w, a1.x, a1.y, a1.z, a1.w};
#pragma unroll
            for (int i = 0; i < 8; i++) {
                unsigned long long ad = dup2(a[i]);
                ffma2(acc[i][0], ad, bp0);
                ffma2(acc[i][1], ad, bp1);
                ffma2(acc[i][2], ad, bp2);
                ffma2(acc[i][3], ad, bp3);
            }
        }

        if (more) {
            // safe without a pre-write sync: all warps passed sync(k0-1), so
            // every warp finished computing on nbuf (== buffer of k0-8) already.
            As[nbuf][lk + 0][lrow] = av.x; As[nbuf][lk + 1][lrow] = av.y;
            As[nbuf][lk + 2][lrow] = av.z; As[nbuf][lk + 3][lrow] = av.w;
            Bs[nbuf][lk + 0][lrow] = bv.x; Bs[nbuf][lk + 1][lrow] = bv.y;
            Bs[nbuf][lk + 2][lrow] = bv.z; Bs[nbuf][lk + 3][lrow] = bv.w;
            __syncthreads();
        }
    }

    float bs[8];
#pragma unroll
    for (int c = 0; c < 8; c++) bs[c] = bias[n0 + tx * 8 + c];
#pragma unroll
    for (int i = 0; i < 8; i++) {
        size_t base = (size_t)(m0 + ty * 8 + i) * 1536 + n0 + tx * 8;
        float2 p0 = unpack2(acc[i][0]);
        float2 p1 = unpack2(acc[i][1]);
        float2 p2 = unpack2(acc[i][2]);
        float2 p3 = unpack2(acc[i][3]);
        float4 o0 = make_float4(p0.x + bs[0], p0.y + bs[1], p1.x + bs[2], p1.y + bs[3]);
        float4 o1 = make_float4(p2.x + bs[4], p2.y + bs[5], p3.x + bs[6], p3.y + bs[7]);
        *(float4*)&g_gx[base]     = o0;
        *(float4*)&g_gx[base + 4] = o1;
    }
}

// =================================================================================
// Kernel B: team-partitioned persistent GRU recurrence (R10 verbatim -- best known).
//   4 teams x 32 CTAs; team tau owns b = 4i + tau; CTA owns units [16c,16c+16).
//   Warp = rowgroup(6 x 8 rows) x kslice(2 x 128 kp) x bhalf(2 x 8 b).
//   Lane = q(8 kp-subs) x p(4 b-pairs). Per lane: 8 rows x 32 k x 2 b.
//   Sync per step: warp0 flag poll -> syncthreads -> stage -> syncthreads ->
//   FMA -> syncthreads -> gate/publish/release. (ONE warp polls; never more.)
// =================================================================================
__global__ __launch_bounds__(NTHR, 1) void gru_rec(const float* __restrict__ whh,
                                                   const float* __restrict__ bhh,
                                                   const int* __restrict__ lens,
                                                   float* __restrict__ out) {
    extern __shared__ __align__(16) float sm[];
    int* sm_lens = (int*)&sm[LENS_OFF];

    const int tid  = threadIdx.x;
    const int tau  = blockIdx.x >> 5;        // team 0..3
    const int c    = blockIdx.x & 31;        // CTA within team
    const int wrp  = tid >> 5;
    const int lane = tid & 31;

    // FMA-phase warp mapping
    const int rg = wrp >> 2;                 // rowgroup 0..5 (8 rows each)
    const int ks = (wrp >> 1) & 1;           // kslice 0..1 (128 kp each)
    const int bh = wrp & 1;                  // bhalf 0..1 (8 b each)
    const int q  = lane >> 2;                // kp-sub 0..7
    const int p  = lane & 3;                 // b-pair 0..3
    const int b0 = bh * 8 + 2 * p;           // team-b
    const int rowbase = rg * 8;

    // gate-phase mapping (tid < 256)
    const int gu = tid & 15;                 // unit-in-CTA
    const int gb = tid >> 4;                 // team-b 0..15 (only valid tid<256)
    const int bglob = 4 * (gb & 15) + tau;
    const int j = 16 * c + gu;

    // ---- preload W slice (48 rows x 512) ----
    for (int idx = tid; idx < 48 * 128; idx += NTHR) {
        int row = idx >> 7;
        int k4  = (idx & 127) << 2;
        int g   = row >> 4;
        int u   = row & 15;
        *(float4*)&sm[WP_OFF + row * WP_ROW + k4] =
            *(const float4*)&whh[(size_t)(g * 512 + 16 * c + u) * 512 + k4];
    }
    if (tid < 16) sm_lens[tid] = lens[4 * tid + tau];

    const unsigned int F = ld_rlx(&g_flag[blockIdx.x]); // monotonic across replays

    float bh_r = 0.f, bh_z = 0.f, bh_n = 0.f;
    if (tid < 256) {
        bh_r = bhh[j];
        bh_z = bhh[512 + j];
        bh_n = bhh[1024 + j];
    }
    // h(0) = 0 for this CTA's 8 kp x 32 floats
    if (tid < 256)
        __stcg(&g_hP[0][tau][8 * c + (tid >> 5)][tid & 31], 0.f);
    __syncthreads();
    const int maxlen_team = sm_lens[0];
    const int ml_bh = sm_lens[bh * 8];       // warp b-half max length (descending)
    const int len_b = (tid < 256) ? sm_lens[gb] : 0;
    if (tid == 0) st_rel(&g_flag[blockIdx.x], F + 1);   // h(0) published

    const unsigned int* fp = &g_flag[(tau << 5) + lane];
    float hreg = 0.f;

    for (int t = 0; t < 1024; t++) {
        if (t < maxlen_team) {
            // gx prefetch (overlaps poll)
            float gxr = 0.f, gxz = 0.f, gxn = 0.f;
            if (tid < 256) {
                const float* gxp = g_gx + (size_t)(t * 64 + bglob) * 1536 + j;
                gxr = gxp[0];
                gxz = gxp[512];
                gxn = gxp[1024];
            }

            // [poll] warp 0 waits for all 32 team CTAs to publish h(t)
            if (wrp == 0) {
                const unsigned int tgt = F + 1 + (unsigned)t;
                while (!__all_sync(0xffffffffu, ld_acq(fp) >= tgt)) {}
            }
            __syncthreads();

            // [stage] team h(t): 256 kp x 32 floats (coalesced L2 reads)
            for (int s = tid; s < 2048; s += NTHR) {
                int kp = s >> 3;
                int f4 = (s & 7) << 2;
                float4 v = __ldcg((const float4*)&g_hP[t & 1][tau][kp][f4]);
                *(float4*)&sm[HS_OFF + kp * HS_ROW + f4] = v;
            }
            __syncthreads();

            // [FMA] 8 rows x 1 b-pair x 32 k per lane (skip if b-half done)
            if (t < ml_bh) {
                unsigned long long accA[8], accB[8];
#pragma unroll
                for (int r = 0; r < 8; r++) { accA[r] = 0ull; accB[r] = 0ull; }

#pragma unroll
                for (int i = 0; i < 8; i++) {
                    int kp1 = ks * 128 + i * 16 + 2 * q;
                    ulonglong2 hA = *(const ulonglong2*)&sm[HS_OFF + kp1 * HS_ROW + 2 * b0];
                    ulonglong2 hB = *(const ulonglong2*)&sm[HS_OFF + (kp1 + 1) * HS_ROW + 2 * b0];
#pragma unroll
                    for (int r = 0; r < 8; r++) {
                        ulonglong2 wv = *(const ulonglong2*)
                            &sm[WP_OFF + (rowbase + r) * WP_ROW + 2 * kp1];
                        ffma2(accA[r], hA.x, wv.x);
                        ffma2(accA[r], hB.x, wv.y);
                        ffma2(accB[r], hA.y, wv.x);
                        ffma2(accB[r], hB.y, wv.y);
                    }
                }

                // fold k-parity + q (xor 4,8,16); q==0 lanes store partials
#pragma unroll
                for (int r = 0; r < 8; r++) {
                    float sA = sum2(accA[r]);
                    float sB = sum2(accB[r]);
                    sA += __shfl_xor_sync(0xffffffffu, sA, 4);
                    sB += __shfl_xor_sync(0xffffffffu, sB, 4);
                    sA += __shfl_xor_sync(0xffffffffu, sA, 8);
                    sB += __shfl_xor_sync(0xffffffffu, sB, 8);
                    sA += __shfl_xor_sync(0xffffffffu, sA, 16);
                    sB += __shfl_xor_sync(0xffffffffu, sB, 16);
                    if (lane < 4) {
                        RED_AT(t & 1, ks, rowbase + r, b0)     = sA;
                        RED_AT(t & 1, ks, rowbase + r, b0 + 1) = sB;
                    }
                }
            }
            __syncthreads();                              // red[t&1] complete

            // [gate] 16 units x 16 team-b
            if (tid < 256) {
                float outv = 0.f;
                if (t < len_b) {
                    float ghr = bh_r + RED_AT(t & 1, 0, gu, gb)      + RED_AT(t & 1, 1, gu, gb);
                    float ghz = bh_z + RED_AT(t & 1, 0, 16 + gu, gb) + RED_AT(t & 1, 1, 16 + gu, gb);
                    float ghn = bh_n + RED_AT(t & 1, 0, 32 + gu, gb) + RED_AT(t & 1, 1, 32 + gu, gb);
                    float r = 1.f / (1.f + __expf(-(gxr + ghr)));
                    float z = 1.f / (1.f + __expf(-(gxz + ghz)));
                    float n = tanhf(gxn + r * ghn);
                    hreg = (1.f - z) * n + z * hreg;
                    outv = hreg;
                }
                // publish h(t+1) unit-pair via shfl partner
                float hpart = __shfl_xor_sync(0xffffffffu, hreg, 1);
                if ((gu & 1) == 0) {
                    float2 v = make_float2(hreg, hpart);
                    __stcg((float2*)&g_hP[(t + 1) & 1][tau][8 * c + (gu >> 1)][2 * gb], v);
                }
                bar_sync(1, 256);                         // all h publishes done
                if (tid == 0) st_rel(&g_flag[blockIdx.x], F + 2 + (unsigned)t);

                out[(size_t)t * 32768 + bglob * 512 + j] = outv;
            }
        } else {
            // whole team finished: zero-fill remaining output rows
            if (tid < 256)
                out[(size_t)t * 32768 + bglob * 512 + j] = 0.f;
        }
    }

    // h_last: [1, B, H]
    if (tid < 256)
        out[(size_t)1024 * 32768 + bglob * 512 + j] = hreg;
}

// =================================================================================
// Inputs (metadata order): x[T,B,I] f32, batch_lengths[B] i32, w_ih[3H,I] f32,
// w_hh[3H,H] f32, b_ih[3H] f32, b_hh[3H] f32.  Output: [T,B,H] then [1,B,H], fp32.
// =================================================================================
extern "C" void kernel_launch(void* const* d_in, const int* in_sizes, int n_in,
                              void* d_out, int out_size) {
    const float* x   = (const float*)d_in[0];
    const int*   len = (const int*)  d_in[1];
    const float* wih = (const float*)d_in[2];
    const float* whh = (const float*)d_in[3];
    const float* bih = (const float*)d_in[4];
    const float* bhh = (const float*)d_in[5];
    float* out = (float*)d_out;

    (void)in_sizes; (void)n_in; (void)out_size;

    cudaFuncSetAttribute(gru_rec, cudaFuncAttributeMaxDynamicSharedMemorySize, SMEM_BYTES);

    gemm_gx<<<dim3(12, 512), 256>>>(x, wih, bih);
    gru_rec<<<NCTA, NTHR, SMEM_BYTES>>>(whh, bhh, len, out);
}

// round 15
// speedup vs baseline: 1.5320x; 1.0854x over previous
#include <cuda_runtime.h>

// Problem constants: T=1024, B=64, I=512, H=512, 3H=1536
#define NCTA 128
#define NTEAMS 8        // 8 teams x 16 CTAs; team tau owns b in {tau, tau+8, ..., tau+56}
#define CPT 16          // CTAs per team; CTA owns units [32c, 32c+32)
#define NTHR 768        // 24 warps: 6 rowgroups(16 rows) x 2 kslices x 2 bhalves(4 b)

// ---------------- device-global scratch (no allocation allowed) ----------------
__device__ float g_gx[100663296];                       // [1024*64, 1536] input gate pre-acts
__device__ __align__(16) float g_hP[2][NTEAMS][256][16]; // [buf][team][kp][tb*2+par]
__device__ unsigned int g_flag[NCTA];                   // per-CTA publish counters (monotonic)

// ---------------- f32x2 packed-math helpers (Blackwell, PTX-only path) ----------
__device__ __forceinline__ void ffma2(unsigned long long &acc, unsigned long long a,
                                      unsigned long long b) {
    asm("fma.rn.f32x2 %0, %1, %2, %0;" : "+l"(acc) : "l"(a), "l"(b));
}
__device__ __forceinline__ unsigned long long dup2(float a) {
    unsigned long long r; asm("mov.b64 %0, {%1, %1};" : "=l"(r) : "f"(a)); return r;
}
__device__ __forceinline__ unsigned long long pack2(float lo, float hi) {
    unsigned long long r; asm("mov.b64 %0, {%1, %2};" : "=l"(r) : "f"(lo), "f"(hi)); return r;
}
__device__ __forceinline__ float sum2(unsigned long long v) {
    float lo, hi; asm("mov.b64 {%0, %1}, %2;" : "=f"(lo), "=f"(hi) : "l"(v)); return lo + hi;
}
__device__ __forceinline__ float2 unpack2(unsigned long long v) {
    float2 f; asm("mov.b64 {%0, %1}, %2;" : "=f"(f.x), "=f"(f.y) : "l"(v)); return f;
}

// ---------------- flag primitives (gpu scope, L2-coherent) -----------------------
__device__ __forceinline__ unsigned int ld_acq(const unsigned int* p) {
    unsigned int v;
    asm volatile("ld.acquire.gpu.global.u32 %0, [%1];" : "=r"(v) : "l"(p) : "memory");
    return v;
}
__device__ __forceinline__ unsigned int ld_rlx(const unsigned int* p) {
    unsigned int v;
    asm volatile("ld.relaxed.gpu.global.u32 %0, [%1];" : "=r"(v) : "l"(p) : "memory");
    return v;
}
__device__ __forceinline__ void st_rel(unsigned int* p, unsigned int v) {
    asm volatile("st.release.gpu.global.u32 [%0], %1;" :: "l"(p), "r"(v) : "memory");
}
__device__ __forceinline__ void bar_sync(int id, int cnt) {
    asm volatile("bar.sync %0, %1;" :: "r"(id), "r"(cnt) : "memory");
}

// ---------------- dynamic SMEM layout (floats) -- rec kernel ---------------------
#define WP_OFF   0                          // W: [96 rows][512]            (196,608 B)
#define WP_ROW   512
#define HS_OFF   (96 * 512)                 // staged h: [256 kp][20 pad]   (20,480 B)
#define HS_ROW   20
#define RED_OFF  (HS_OFF + 256 * HS_ROW)    // red: [2 par][2 ks][96][9]    (13,824 B)
#define LENS_OFF (RED_OFF + 2 * 2 * 96 * 9)
#define SMEM_FLOATS (LENS_OFF + 16)
#define SMEM_BYTES  (SMEM_FLOATS * 4)       // 230,976 B (< 232,448 cap)
#define RED_AT(par, ksi, row, b) sm[RED_OFF + (((par) * 2 + (ksi)) * 96 + (row)) * 9 + (b)]

// =================================================================================
// Kernel A: gx[m][n] = sum_k X[m][k] * W[n][k] + bias[n]  (R14 double-buffered)
// =================================================================================
__global__ __launch_bounds__(256) void gemm_gx(const float* __restrict__ X,
                                               const float* __restrict__ W,
                                               const float* __restrict__ bias) {
    __shared__ __align__(16) float As[2][8][128];
    __shared__ __align__(16) float Bs[2][8][128];
    const int tid = threadIdx.x;
    const int m0 = blockIdx.y * 128;
    const int n0 = blockIdx.x * 128;
    const int tx = tid & 15;
    const int ty = tid >> 4;
    const int lrow = tid >> 1;
    const int lk = (tid & 1) * 4;

    unsigned long long acc[8][4];
#pragma unroll
    for (int i = 0; i < 8; i++)
#pragma unroll
        for (int jp = 0; jp < 4; jp++) acc[i][jp] = 0ull;

    const float* xg = X + (size_t)(m0 + lrow) * 512 + lk;
    const float* wg = W + (size_t)(n0 + lrow) * 512 + lk;

    {
        float4 av = *(const float4*)(xg);
        float4 bv = *(const float4*)(wg);
        As[0][lk + 0][lrow] = av.x; As[0][lk + 1][lrow] = av.y;
        As[0][lk + 2][lrow] = av.z; As[0][lk + 3][lrow] = av.w;
        Bs[0][lk + 0][lrow] = bv.x; Bs[0][lk + 1][lrow] = bv.y;
        Bs[0][lk + 2][lrow] = bv.z; Bs[0][lk + 3][lrow] = bv.w;
    }
    __syncthreads();

    for (int k0 = 0; k0 < 512; k0 += 8) {
        const int buf  = (k0 >> 3) & 1;
        const int nbuf = buf ^ 1;
        const bool more = (k0 + 8) < 512;

        float4 av, bv;
        if (more) {
            av = *(const float4*)(xg + k0 + 8);
            bv = *(const float4*)(wg + k0 + 8);
        }

#pragma unroll
        for (int kk = 0; kk < 8; kk++) {
            float4 a0 = *(const float4*)&As[buf][kk][ty * 8];
            float4 a1 = *(const float4*)&As[buf][kk][ty * 8 + 4];
            float4 b0 = *(const float4*)&Bs[buf][kk][tx * 8];
            float4 b1 = *(const float4*)&Bs[buf][kk][tx * 8 + 4];
            unsigned long long bp0 = pack2(b0.x, b0.y);
            unsigned long long bp1 = pack2(b0.z, b0.w);
            unsigned long long bp2 = pack2(b1.x, b1.y);
            unsigned long long bp3 = pack2(b1.z, b1.w);
            float a[8] = {a0.x, a0.y, a0.z, a0.w, a1.x, a1.y, a1.z, a1.w};
#pragma unroll
            for (int i = 0; i < 8; i++) {
                unsigned long long ad = dup2(a[i]);
                ffma2(acc[i][0], ad, bp0);
                ffma2(acc[i][1], ad, bp1);
                ffma2(acc[i][2], ad, bp2);
                ffma2(acc[i][3], ad, bp3);
            }
        }

        if (more) {
            As[nbuf][lk + 0][lrow] = av.x; As[nbuf][lk + 1][lrow] = av.y;
            As[nbuf][lk + 2][lrow] = av.z; As[nbuf][lk + 3][lrow] = av.w;
            Bs[nbuf][lk + 0][lrow] = bv.x; Bs[nbuf][lk + 1][lrow] = bv.y;
            Bs[nbuf][lk + 2][lrow] = bv.z; Bs[nbuf][lk + 3][lrow] = bv.w;
            __syncthreads();
        }
    }

    float bs[8];
#pragma unroll
    for (int c = 0; c < 8; c++) bs[c] = bias[n0 + tx * 8 + c];
#pragma unroll
    for (int i = 0; i < 8; i++) {
        size_t base = (size_t)(m0 + ty * 8 + i) * 1536 + n0 + tx * 8;
        float2 p0 = unpack2(acc[i][0]);
        float2 p1 = unpack2(acc[i][1]);
        float2 p2 = unpack2(acc[i][2]);
        float2 p3 = unpack2(acc[i][3]);
        float4 o0 = make_float4(p0.x + bs[0], p0.y + bs[1], p1.x + bs[2], p1.y + bs[3]);
        float4 o1 = make_float4(p2.x + bs[4], p2.y + bs[5], p3.x + bs[6], p3.y + bs[7]);
        *(float4*)&g_gx[base]     = o0;
        *(float4*)&g_gx[base + 4] = o1;
    }
}

// =================================================================================
// Kernel B: persistent GRU recurrence, 8 teams x 16 CTAs (halved sync domain).
//   Team tau owns b = 8i + tau (i = 0..7, lengths descending). CTA owns units
//   [32c, 32c+32) -> 96 gate rows (196KB W in SMEM). Team h = 16KB/step staged.
//   Warp = rowgroup(6 x 16 rows) x kslice(2 x 128 kp) x bhalf(2 x 4 b).
//   Lane = q(8 kp-subs) x s(2 row-halves) x p(2 b-pairs): 8 rows x 32 k x 2 b.
//   Sync per step: warp0 polls 16 team flags -> sync -> stage -> sync -> FMA ->
//   sync -> gate (256 thr: 32 units x 8 b) -> publish + release.
// =================================================================================
__global__ __launch_bounds__(NTHR, 1) void gru_rec(const float* __restrict__ whh,
                                                   const float* __restrict__ bhh,
                                                   const int* __restrict__ lens,
                                                   float* __restrict__ out) {
    extern __shared__ __align__(16) float sm[];
    int* sm_lens = (int*)&sm[LENS_OFF];

    const int tid  = threadIdx.x;
    const int tau  = blockIdx.x >> 4;        // team 0..7
    const int c    = blockIdx.x & 15;        // CTA within team
    const int wrp  = tid >> 5;
    const int lane = tid & 31;

    // FMA-phase warp mapping
    const int rg = wrp >> 2;                 // rowgroup 0..5 (16 rows each)
    const int ks = (wrp >> 1) & 1;           // kslice 0..1 (128 kp each)
    const int bh = wrp & 1;                  // bhalf 0..1 (4 b each)
    const int q  = lane >> 2;                // kp-sub 0..7
    const int s  = (lane >> 1) & 1;          // row-half 0..1 (8 rows each)
    const int p  = lane & 1;                 // b-pair 0..1
    const int b0 = bh * 4 + 2 * p;           // team-b
    const int rowbase = rg * 16 + s * 8;

    // gate-phase mapping (tid < 256): 32 units x 8 team-b
    const int gu = tid & 31;                 // unit-in-CTA
    const int gb = (tid >> 5) & 7;           // team-b (valid for tid < 256)
    const int bglob = 8 * gb + tau;
    const int j = 32 * c + gu;

    // ---- preload W slice (96 rows x 512) ----
    for (int idx = tid; idx < 96 * 128; idx += NTHR) {
        int row = idx >> 7;
        int k4  = (idx & 127) << 2;
        int g   = row >> 5;
        int u   = row & 31;
        *(float4*)&sm[WP_OFF + row * WP_ROW + k4] =
            *(const float4*)&whh[(size_t)(g * 512 + 32 * c + u) * 512 + k4];
    }
    if (tid < 8) sm_lens[tid] = lens[8 * tid + tau];

    const unsigned int F = ld_rlx(&g_flag[blockIdx.x]); // monotonic across replays

    float bh_r = 0.f, bh_z = 0.f, bh_n = 0.f;
    if (tid < 256) {
        bh_r = bhh[j];
        bh_z = bhh[512 + j];
        bh_n = bhh[1024 + j];
    }
    // h(0) = 0 for this CTA's 16 kp x 16 floats
    if (tid < 256)
        __stcg(&g_hP[0][tau][16 * c + (tid >> 4)][tid & 15], 0.f);
    __syncthreads();
    const int maxlen_team = sm_lens[0];
    const int ml_bh = sm_lens[bh * 4];       // warp b-half max length (descending)
    const int len_b = (tid < 256) ? sm_lens[gb] : 0;
    if (tid == 0) st_rel(&g_flag[blockIdx.x], F + 1);   // h(0) published

    const unsigned int* fp = &g_flag[(tau << 4) + (lane & 15)];
    float hreg = 0.f;

    for (int t = 0; t < 1024; t++) {
        if (t < maxlen_team) {
            // gx prefetch (overlaps poll)
            float gxr = 0.f, gxz = 0.f, gxn = 0.f;
            if (tid < 256) {
                const float* gxp = g_gx + (size_t)(t * 64 + bglob) * 1536 + j;
                gxr = gxp[0];
                gxz = gxp[512];
                gxn = gxp[1024];
            }

            // [poll] warp 0 ONLY waits for all 16 team CTAs to publish h(t)
            if (wrp == 0) {
                const unsigned int tgt = F + 1 + (unsigned)t;
                while (!__all_sync(0xffffffffu, ld_acq(fp) >= tgt)) {}
            }
            __syncthreads();

            // [stage] team h(t): 256 kp x 16 floats = 16KB (coalesced L2 reads)
            for (int sIdx = tid; sIdx < 1024; sIdx += NTHR) {
                int kp = sIdx >> 2;
                int f4 = (sIdx & 3) << 2;
                float4 v = __ldcg((const float4*)&g_hP[t & 1][tau][kp][f4]);
                *(float4*)&sm[HS_OFF + kp * HS_ROW + f4] = v;
            }
            __syncthreads();

            // [FMA] 8 rows x 32 k x 2 b per lane (skip if b-half done)
            if (t < ml_bh) {
                unsigned long long accA[8], accB[8];
#pragma unroll
                for (int r = 0; r < 8; r++) { accA[r] = 0ull; accB[r] = 0ull; }

#pragma unroll
                for (int i = 0; i < 8; i++) {
                    int kp1 = ks * 128 + i * 16 + 2 * q;
                    ulonglong2 hA = *(const ulonglong2*)&sm[HS_OFF + kp1 * HS_ROW + 2 * b0];
                    ulonglong2 hB = *(const ulonglong2*)&sm[HS_OFF + (kp1 + 1) * HS_ROW + 2 * b0];
#pragma unroll
                    for (int r = 0; r < 8; r++) {
                        ulonglong2 wv = *(const ulonglong2*)
                            &sm[WP_OFF + (rowbase + r) * WP_ROW + 2 * kp1];
                        ffma2(accA[r], hA.x, wv.x);
                        ffma2(accA[r], hB.x, wv.y);
                        ffma2(accB[r], hA.y, wv.x);
                        ffma2(accB[r], hB.y, wv.y);
                    }
                }

                // fold q (xor 4,8,16 = q bits); lanes 0..3 (q==0) store partials
#pragma unroll
                for (int r = 0; r < 8; r++) {
                    float sA = sum2(accA[r]);
                    float sB = sum2(accB[r]);
                    sA += __shfl_xor_sync(0xffffffffu, sA, 4);
                    sB += __shfl_xor_sync(0xffffffffu, sB, 4);
                    sA += __shfl_xor_sync(0xffffffffu, sA, 8);
                    sB += __shfl_xor_sync(0xffffffffu, sB, 8);
                    sA += __shfl_xor_sync(0xffffffffu, sA, 16);
                    sB += __shfl_xor_sync(0xffffffffu, sB, 16);
                    if (lane < 4) {
                        RED_AT(t & 1, ks, rowbase + r, b0)     = sA;
                        RED_AT(t & 1, ks, rowbase + r, b0 + 1) = sB;
                    }
                }
            }
            __syncthreads();                              // red[t&1] complete

            // [gate] 32 units x 8 team-b
            if (tid < 256) {
                float outv = 0.f;
                if (t < len_b) {
                    float ghr = bh_r + RED_AT(t & 1, 0, gu, gb)      + RED_AT(t & 1, 1, gu, gb);
                    float ghz = bh_z + RED_AT(t & 1, 0, 32 + gu, gb) + RED_AT(t & 1, 1, 32 + gu, gb);
                    float ghn = bh_n + RED_AT(t & 1, 0, 64 + gu, gb) + RED_AT(t & 1, 1, 64 + gu, gb);
                    float r = 1.f / (1.f + __expf(-(gxr + ghr)));
                    float z = 1.f / (1.f + __expf(-(gxz + ghz)));
                    float n = tanhf(gxn + r * ghn);
                    hreg = (1.f - z) * n + z * hreg;
                    outv = hreg;
                }
                // publish h(t+1) unit-pair via shfl partner (gu, gu^1 share gb)
                float hpart = __shfl_xor_sync(0xffffffffu, hreg, 1);
                if ((gu & 1) == 0) {
                    float2 v = make_float2(hreg, hpart);
                    __stcg((float2*)&g_hP[(t + 1) & 1][tau][16 * c + (gu >> 1)][2 * gb], v);
                }
                bar_sync(1, 256);                         // all h publishes done
                if (tid == 0) st_rel(&g_flag[blockIdx.x], F + 2 + (unsigned)t);

                out[(size_t)t * 32768 + bglob * 512 + j] = outv;
            }
        } else {
            // whole team finished: zero-fill remaining output rows
            if (tid < 256)
                out[(size_t)t * 32768 + bglob * 512 + j] = 0.f;
        }
    }

    // h_last: [1, B, H]
    if (tid < 256)
        out[(size_t)1024 * 32768 + bglob * 512 + j] = hreg;
}

// =================================================================================
// Inputs (metadata order): x[T,B,I] f32, batch_lengths[B] i32, w_ih[3H,I] f32,
// w_hh[3H,H] f32, b_ih[3H] f32, b_hh[3H] f32.  Output: [T,B,H] then [1,B,H], fp32.
// =================================================================================
extern "C" void kernel_launch(void* const* d_in, const int* in_sizes, int n_in,
                              void* d_out, int out_size) {
    const float* x   = (const float*)d_in[0];
    const int*   len = (const int*)  d_in[1];
    const float* wih = (const float*)d_in[2];
    const float* whh = (const float*)d_in[3];
    const float* bih = (const float*)d_in[4];
    const float* bhh = (const float*)d_in[5];
    float* out = (float*)d_out;

    (void)in_sizes; (void)n_in; (void)out_size;

    cudaFuncSetAttribute(gru_rec, cudaFuncAttributeMaxDynamicSharedMemorySize, SMEM_BYTES);

    gemm_gx<<<dim3(12, 512), 256>>>(x, wih, bih);
    gru_rec<<<NCTA, NTHR, SMEM_BYTES>>>(whh, bhh, len, out);
}